// round 12
// baseline (speedup 1.0000x reference)
#include <cuda_runtime.h>
#include <cuda_fp16.h>
#include <cstdint>

#define N_NODES 50000
#define D_IN    256
#define D_H     256
#define D_OUT   128
#define MAX_E   1600000
#define MAX_EL  100000
#define SCAN_B  49          // ceil(50000/1024)

// ---------------- scratch (device globals; no allocation) ----------------
__device__ int    g_is64;
__device__ int    g_counts[N_NODES];
__device__ int    g_offsets[N_NODES + 1];
__device__ int    g_cursor[N_NODES];
__device__ int    g_bsums[64];
__device__ float  g_dis[N_NODES];
__device__ int    g_src_sorted[MAX_E];
__device__ __half g_w1t[D_H * D_IN];       // W1^T [n][k] half
__device__ __half g_w2t[D_OUT * D_H];      // W2^T [n][k] half
__device__ __half g_hh1[N_NODES * D_H];    // half(dis[i] * (x@W1)[i])
__device__ __half g_z1h[N_NODES * D_H];    // relu(agg + b1) half (GEMM2 A)
__device__ __half g_hh2[N_NODES * D_OUT];  // half(dis[i] * (z1@W2)[i])
__device__ float  g_z2[N_NODES * D_OUT];   // agg + b2 (fp32, decode operand)

// ---------------- fused init: weight transpose+convert, zero counts, detect ----------------
__global__ void init_kernel(const float* __restrict__ W1,
                            const float* __restrict__ W2,
                            const int* __restrict__ raw) {
    int i = blockIdx.x * blockDim.x + threadIdx.x;
    if (i < D_IN * D_H) {
        int k = i >> 8, n = i & 255;                 // W1[k][n]
        g_w1t[n * D_IN + k] = __float2half(W1[i]);
    }
    if (i < D_H * D_OUT) {
        int k = i >> 7, n = i & 127;                 // W2[k][n]
        g_w2t[n * D_H + k] = __float2half(W2[i]);
    }
    if (i < N_NODES) g_counts[i] = 0;
    if (blockIdx.x == 0 && threadIdx.x < 32) {
        int nz = 0;
        for (int j = threadIdx.x; j < 256; j += 32)
            nz |= (raw[2 * j + 1] != 0);
        unsigned m = __ballot_sync(0xffffffffu, nz);
        if (threadIdx.x == 0) g_is64 = (m == 0);
    }
}

__global__ void count_kernel(const void* __restrict__ raw, int E) {
    int i = blockIdx.x * blockDim.x + threadIdx.x;
    if (i >= E) return;
    int d;
    if (g_is64) d = (int)((const long long*)raw)[E + i];
    else        d = ((const int*)raw)[E + i];
    atomicAdd(&g_counts[d], 1);
}

__global__ void dis_kernel() {
    int i = blockIdx.x * blockDim.x + threadIdx.x;
    if (i < N_NODES) g_dis[i] = rsqrtf((float)(g_counts[i] + 1));
}

// ---------------- 3-phase parallel exclusive scan ----------------
__global__ __launch_bounds__(1024) void scan_part1(int n) {
    int i = blockIdx.x * 1024 + threadIdx.x;
    int v = (i < n) ? g_counts[i] : 0;
    int lane = threadIdx.x & 31, wid = threadIdx.x >> 5;

    int x = v;
    #pragma unroll
    for (int o = 1; o < 32; o <<= 1) {
        int t = __shfl_up_sync(0xffffffffu, x, o);
        if (lane >= o) x += t;
    }
    __shared__ int wsum[32];
    if (lane == 31) wsum[wid] = x;
    __syncthreads();
    if (wid == 0) {
        int ws = wsum[lane];
        #pragma unroll
        for (int o = 1; o < 32; o <<= 1) {
            int t = __shfl_up_sync(0xffffffffu, ws, o);
            if (lane >= o) ws += t;
        }
        wsum[lane] = ws;
    }
    __syncthreads();
    int incl = x + (wid > 0 ? wsum[wid - 1] : 0);
    if (i < n) g_offsets[i] = incl - v;              // local exclusive
    if (threadIdx.x == 1023) g_bsums[blockIdx.x] = incl;
}

__global__ void scan_part2(int nb, int n) {
    __shared__ int ws[2];
    int lane = threadIdx.x & 31, w = threadIdx.x >> 5;
    int v = (threadIdx.x < nb) ? g_bsums[threadIdx.x] : 0;
    int x = v;
    #pragma unroll
    for (int o = 1; o < 32; o <<= 1) {
        int t = __shfl_up_sync(0xffffffffu, x, o);
        if (lane >= o) x += t;
    }
    if (lane == 31) ws[w] = x;
    __syncthreads();
    int incl = x + ((w == 1) ? ws[0] : 0);
    if (threadIdx.x < nb) g_bsums[threadIdx.x] = incl - v;   // exclusive
    if (threadIdx.x == nb - 1) g_offsets[n] = incl;
}

__global__ __launch_bounds__(1024) void scan_part3(int n) {
    int i = blockIdx.x * 1024 + threadIdx.x;
    if (i < n) {
        int off = g_offsets[i] + g_bsums[blockIdx.x];
        g_offsets[i] = off;
        g_cursor[i]  = off;
    }
}

__global__ void fill_kernel(const void* __restrict__ raw, int E) {
    int i = blockIdx.x * blockDim.x + threadIdx.x;
    if (i >= E) return;
    int s, d;
    if (g_is64) {
        const long long* p = (const long long*)raw;
        s = (int)p[i]; d = (int)p[E + i];
    } else {
        const int* p = (const int*)raw;
        s = p[i]; d = p[E + i];
    }
    int pos = atomicAdd(&g_cursor[d], 1);
    g_src_sorted[pos] = s;
}

// ---------------- fp16 tensor-core GEMM with ldmatrix fragment loads ----------------
#define LDH 40   // padded row (halves): 8 rows @ 20-word stride hit distinct banks

__device__ __forceinline__ void ldmx4(unsigned& r0, unsigned& r1,
                                      unsigned& r2, unsigned& r3, unsigned addr) {
    asm volatile("ldmatrix.sync.aligned.m8n8.x4.shared.b16 {%0,%1,%2,%3}, [%4];"
                 : "=r"(r0), "=r"(r1), "=r"(r2), "=r"(r3) : "r"(addr));
}

template<bool A_HALF>
__global__ __launch_bounds__(256) void hgemm_kernel(
    const void* __restrict__ Ain, const __half* __restrict__ Bt,
    __half* __restrict__ Ch, const float* __restrict__ dis,
    int M, int N, int K)
{
    __shared__ __half As[128][LDH];   // [m][k]
    __shared__ __half Bs[128][LDH];   // [n][k]

    const int tid  = threadIdx.x;
    const int lane = tid & 31;
    const int w    = tid >> 5;
    const int wm   = (w & 3) * 32;
    const int wn   = (w >> 2) * 64;
    const int bm   = blockIdx.y * 128;
    const int bn   = blockIdx.x * 128;
    const int r    = lane >> 2;
    const int c    = lane & 3;

    float acc[2][8][4];
    #pragma unroll
    for (int i = 0; i < 2; i++)
        #pragma unroll
        for (int j = 0; j < 8; j++)
            #pragma unroll
            for (int q = 0; q < 4; q++) acc[i][j][q] = 0.f;

    const int sr = tid & 127;
    const int sq = tid >> 7;            // 0/1 -> k-offset sq*16
    const int amg = bm + sr;
    const bool arow_ok = (amg < M);

    const float* Af = (const float*)Ain;
    const __half* Ah = (const __half*)Ain;

    float4 fa[4];
    uint4  ha[2];
    uint4  hb[2];

    const int ntiles = K / 32;

    // ldmatrix per-lane address components
    const int lq = lane >> 3, lr8 = lane & 7;
    const unsigned as_base = (unsigned)__cvta_generic_to_shared(&As[0][0]);
    const unsigned bs_base = (unsigned)__cvta_generic_to_shared(&Bs[0][0]);
    // A matrices order: q0=(m0-7,k0-7) q1=(m8-15,k0-7) q2=(m0-7,k8-15) q3=(m8-15,k8-15)
    const int a_row = (lq & 1) * 8 + lr8;
    const int a_col = (lq >> 1) * 8;
    // B matrices order: q0=(n0-7,k0-7) q1=(n0-7,k8-15) q2=(n8-15,k0-7) q3=(n8-15,k8-15)
    const int b_row = (lq >> 1) * 8 + lr8;
    const int b_col = (lq & 1) * 8;

    {
        int k0 = sq * 16;
        if (A_HALF) {
            if (arow_ok) {
                ha[0] = *(const uint4*)&Ah[(long long)amg * K + k0];
                ha[1] = *(const uint4*)&Ah[(long long)amg * K + k0 + 8];
            } else { ha[0] = make_uint4(0,0,0,0); ha[1] = make_uint4(0,0,0,0); }
        } else {
            #pragma unroll
            for (int i = 0; i < 4; i++)
                fa[i] = arow_ok ? *(const float4*)&Af[(long long)amg * K + k0 + i * 4]
                                : make_float4(0.f,0.f,0.f,0.f);
        }
        hb[0] = *(const uint4*)&Bt[(long long)(bn + sr) * K + k0];
        hb[1] = *(const uint4*)&Bt[(long long)(bn + sr) * K + k0 + 8];
    }

    for (int kt = 0; kt < ntiles; kt++) {
        __syncthreads();
        if (A_HALF) {
            *(uint4*)&As[sr][sq * 16]     = ha[0];
            *(uint4*)&As[sr][sq * 16 + 8] = ha[1];
        } else {
            __half2 h8[8];
            h8[0] = __floats2half2_rn(fa[0].x, fa[0].y);
            h8[1] = __floats2half2_rn(fa[0].z, fa[0].w);
            h8[2] = __floats2half2_rn(fa[1].x, fa[1].y);
            h8[3] = __floats2half2_rn(fa[1].z, fa[1].w);
            h8[4] = __floats2half2_rn(fa[2].x, fa[2].y);
            h8[5] = __floats2half2_rn(fa[2].z, fa[2].w);
            h8[6] = __floats2half2_rn(fa[3].x, fa[3].y);
            h8[7] = __floats2half2_rn(fa[3].z, fa[3].w);
            *(uint4*)&As[sr][sq * 16]     = *(uint4*)&h8[0];
            *(uint4*)&As[sr][sq * 16 + 8] = *(uint4*)&h8[4];
        }
        *(uint4*)&Bs[sr][sq * 16]     = hb[0];
        *(uint4*)&Bs[sr][sq * 16 + 8] = hb[1];
        __syncthreads();

        if (kt + 1 < ntiles) {
            int k0 = (kt + 1) * 32 + sq * 16;
            if (A_HALF) {
                if (arow_ok) {
                    ha[0] = *(const uint4*)&Ah[(long long)amg * K + k0];
                    ha[1] = *(const uint4*)&Ah[(long long)amg * K + k0 + 8];
                }
            } else {
                #pragma unroll
                for (int i = 0; i < 4; i++)
                    fa[i] = arow_ok ? *(const float4*)&Af[(long long)amg * K + k0 + i * 4]
                                    : make_float4(0.f,0.f,0.f,0.f);
            }
            hb[0] = *(const uint4*)&Bt[(long long)(bn + sr) * K + k0];
            hb[1] = *(const uint4*)&Bt[(long long)(bn + sr) * K + k0 + 8];
        }

        #pragma unroll
        for (int ks = 0; ks < 2; ks++) {
            int kk = ks * 16;
            unsigned af[2][4];
            #pragma unroll
            for (int tm = 0; tm < 2; tm++) {
                unsigned addr = as_base +
                    (unsigned)(((wm + tm * 16 + a_row) * LDH + kk + a_col) * 2);
                ldmx4(af[tm][0], af[tm][1], af[tm][2], af[tm][3], addr);
            }
            unsigned bf[8][2];
            #pragma unroll
            for (int tnp = 0; tnp < 4; tnp++) {
                unsigned addr = bs_base +
                    (unsigned)(((wn + tnp * 16 + b_row) * LDH + kk + b_col) * 2);
                ldmx4(bf[2*tnp][0], bf[2*tnp][1],
                      bf[2*tnp+1][0], bf[2*tnp+1][1], addr);
            }
            #pragma unroll
            for (int tm = 0; tm < 2; tm++)
                #pragma unroll
                for (int tn = 0; tn < 8; tn++) {
                    asm volatile(
                        "mma.sync.aligned.m16n8k16.row.col.f32.f16.f16.f32 "
                        "{%0,%1,%2,%3}, {%4,%5,%6,%7}, {%8,%9}, {%0,%1,%2,%3};"
                        : "+f"(acc[tm][tn][0]), "+f"(acc[tm][tn][1]),
                          "+f"(acc[tm][tn][2]), "+f"(acc[tm][tn][3])
                        : "r"(af[tm][0]), "r"(af[tm][1]),
                          "r"(af[tm][2]), "r"(af[tm][3]),
                          "r"(bf[tn][0]), "r"(bf[tn][1]));
                }
        }
    }

    #pragma unroll
    for (int tm = 0; tm < 2; tm++) {
        int row0 = bm + wm + tm * 16 + r;
        int row1 = row0 + 8;
        float s0 = (row0 < M) ? dis[row0] : 0.f;
        float s1 = (row1 < M) ? dis[row1] : 0.f;
        #pragma unroll
        for (int tn = 0; tn < 8; tn++) {
            int col = bn + wn + tn * 8 + c * 2;
            if (row0 < M) {
                __half2 hv = __floats2half2_rn(acc[tm][tn][0] * s0,
                                               acc[tm][tn][1] * s0);
                *(__half2*)&Ch[(long long)row0 * N + col] = hv;
            }
            if (row1 < M) {
                __half2 hv = __floats2half2_rn(acc[tm][tn][2] * s1,
                                               acc[tm][tn][3] * s1);
                *(__half2*)&Ch[(long long)row1 * N + col] = hv;
            }
        }
    }
}

// ---------------- aggregation (half gathers, pre-scaled) ----------------
template<int D, bool RELU, bool OUT_HALF>
__global__ __launch_bounds__(256) void agg_half_kernel(
    const __half* __restrict__ HH, void* __restrict__ Zout,
    const float* __restrict__ bias)
{
    constexpr int TPN = D / 4;
    constexpr int NPB = 256 / TPN;
    const int node = blockIdx.x * NPB + threadIdx.x / TPN;
    const int t    = threadIdx.x % TPN;
    if (node >= N_NODES) return;

    const float di = g_dis[node];
    const uint2* Hq = (const uint2*)HH;

    uint2 sv = Hq[(long long)node * TPN + t];
    float2 s0 = __half22float2(*(__half2*)&sv.x);
    float2 s1 = __half22float2(*(__half2*)&sv.y);
    float a0 = s0.x, a1 = s0.y, a2 = s1.x, a3 = s1.y;

    int e   = g_offsets[node];
    int end = g_offsets[node + 1];

    for (; e + 4 <= end; e += 4) {
        int n0 = g_src_sorted[e + 0];
        int n1 = g_src_sorted[e + 1];
        int n2 = g_src_sorted[e + 2];
        int n3 = g_src_sorted[e + 3];
        uint2 v0 = Hq[(long long)n0 * TPN + t];
        uint2 v1 = Hq[(long long)n1 * TPN + t];
        uint2 v2 = Hq[(long long)n2 * TPN + t];
        uint2 v3 = Hq[(long long)n3 * TPN + t];
        float2 p;
        p = __half22float2(*(__half2*)&v0.x); a0 += p.x; a1 += p.y;
        p = __half22float2(*(__half2*)&v0.y); a2 += p.x; a3 += p.y;
        p = __half22float2(*(__half2*)&v1.x); a0 += p.x; a1 += p.y;
        p = __half22float2(*(__half2*)&v1.y); a2 += p.x; a3 += p.y;
        p = __half22float2(*(__half2*)&v2.x); a0 += p.x; a1 += p.y;
        p = __half22float2(*(__half2*)&v2.y); a2 += p.x; a3 += p.y;
        p = __half22float2(*(__half2*)&v3.x); a0 += p.x; a1 += p.y;
        p = __half22float2(*(__half2*)&v3.y); a2 += p.x; a3 += p.y;
    }
    for (; e < end; e++) {
        int s = g_src_sorted[e];
        uint2 v = Hq[(long long)s * TPN + t];
        float2 p;
        p = __half22float2(*(__half2*)&v.x); a0 += p.x; a1 += p.y;
        p = __half22float2(*(__half2*)&v.y); a2 += p.x; a3 += p.y;
    }

    const float4 bv = *(const float4*)&bias[t * 4];
    float o0 = a0 * di + bv.x;
    float o1 = a1 * di + bv.y;
    float o2 = a2 * di + bv.z;
    float o3 = a3 * di + bv.w;
    if (RELU) {
        o0 = fmaxf(o0, 0.f); o1 = fmaxf(o1, 0.f);
        o2 = fmaxf(o2, 0.f); o3 = fmaxf(o3, 0.f);
    }
    if (OUT_HALF) {
        __half2 h0 = __floats2half2_rn(o0, o1);
        __half2 h1 = __floats2half2_rn(o2, o3);
        uint2 st; st.x = *(unsigned*)&h0; st.y = *(unsigned*)&h1;
        *(uint2*)&((__half*)Zout)[(long long)node * D + t * 4] = st;
    } else {
        float4 out = make_float4(o0, o1, o2, o3);
        *(float4*)&((float*)Zout)[(long long)node * D + t * 4] = out;
    }
}

// ---------------- decode: y[e] = dot(z2[a], z2[b]) ----------------
__global__ void decode_kernel(const void* __restrict__ eli_raw,
                              const float* __restrict__ Z,
                              float* __restrict__ y, int EL)
{
    int gw   = (blockIdx.x * blockDim.x + threadIdx.x) >> 5;
    int lane = threadIdx.x & 31;
    if (gw >= EL) return;
    int a, b;
    if (g_is64) {
        const long long* p = (const long long*)eli_raw;
        a = (int)p[gw]; b = (int)p[EL + gw];
    } else {
        const int* p = (const int*)eli_raw;
        a = p[gw]; b = p[EL + gw];
    }
    float4 za = *(const float4*)&Z[(long long)a * 128 + lane * 4];
    float4 zb = *(const float4*)&Z[(long long)b * 128 + lane * 4];
    float s = za.x * zb.x + za.y * zb.y + za.z * zb.z + za.w * zb.w;
    #pragma unroll
    for (int o = 16; o; o >>= 1) s += __shfl_down_sync(0xffffffffu, s, o);
    if (lane == 0) y[gw] = s;
}

// ---------------- launch ----------------
extern "C" void kernel_launch(void* const* d_in, const int* in_sizes, int n_in,
                              void* d_out, int out_size)
{
    const float* x   = (const float*)d_in[0];
    const void*  ei  = d_in[1];
    const void*  eli = d_in[2];
    const float* W1  = (const float*)d_in[3];
    const float* b1  = (const float*)d_in[4];
    const float* W2  = (const float*)d_in[5];
    const float* b2  = (const float*)d_in[6];
    float*       y   = (float*)d_out;

    const int E  = in_sizes[1] / 2;
    const int EL = in_sizes[2] / 2;

    __half *hh1p, *z1hp, *hh2p, *w1tp, *w2tp;
    float  *z2p, *disp;
    cudaGetSymbolAddress((void**)&hh1p, g_hh1);
    cudaGetSymbolAddress((void**)&z1hp, g_z1h);
    cudaGetSymbolAddress((void**)&hh2p, g_hh2);
    cudaGetSymbolAddress((void**)&z2p,  g_z2);
    cudaGetSymbolAddress((void**)&disp, g_dis);
    cudaGetSymbolAddress((void**)&w1tp, g_w1t);
    cudaGetSymbolAddress((void**)&w2tp, g_w2t);

    const int TB = 256;
    init_kernel<<<(D_IN * D_H + TB - 1) / TB, TB>>>(W1, W2, (const int*)ei);
    count_kernel<<<(E + TB - 1) / TB, TB>>>(ei, E);
    dis_kernel<<<(N_NODES + TB - 1) / TB, TB>>>();
    // slot 3: layer-1 GEMM (profiled)
    {
        dim3 grid(D_H / 128, (N_NODES + 127) / 128);
        hgemm_kernel<false><<<grid, 256>>>(x, w1tp, hh1p, disp, N_NODES, D_H, D_IN);
    }
    scan_part1<<<SCAN_B, 1024>>>(N_NODES);
    scan_part2<<<1, 64>>>(SCAN_B, N_NODES);
    scan_part3<<<SCAN_B, 1024>>>(N_NODES);
    fill_kernel<<<(E + TB - 1) / TB, TB>>>(ei, E);
    agg_half_kernel<D_H, true, true><<<(N_NODES + 3) / 4, 256>>>(hh1p, z1hp, b1);
    {
        dim3 grid(D_OUT / 128, (N_NODES + 127) / 128);
        hgemm_kernel<true><<<grid, 256>>>(z1hp, w2tp, hh2p, disp, N_NODES, D_OUT, D_H);
    }
    agg_half_kernel<D_OUT, false, false><<<(N_NODES + 7) / 8, 256>>>(hh2p, z2p, b2);
    decode_kernel<<<(EL * 32 + TB - 1) / TB, TB>>>(eli, z2p, y, EL);
}

// round 15
// speedup vs baseline: 1.1330x; 1.1330x over previous
#include <cuda_runtime.h>
#include <cuda_fp16.h>
#include <cstdint>

#define N_NODES 50000
#define D_IN    256
#define D_H     256
#define D_OUT   128
#define MAX_E   1600000
#define MAX_EL  100000
#define SCAN_B  49          // ceil(50000/1024)

// ---------------- scratch (device globals; no allocation) ----------------
__device__ int    g_is64;
__device__ int    g_counts[N_NODES];
__device__ int    g_offsets[N_NODES + 1];
__device__ int    g_cursor[N_NODES];
__device__ int    g_bsums[64];
__device__ float  g_dis[N_NODES];
__device__ int    g_src_sorted[MAX_E];
__device__ __half g_xh[N_NODES * D_IN];    // half(x)
__device__ __half g_w1t[D_H * D_IN];       // W1^T [n][k] half
__device__ __half g_w2t[D_OUT * D_H];      // W2^T [n][k] half
__device__ __half g_hh1[N_NODES * D_H];    // half(dis[i] * (x@W1)[i])
__device__ __half g_z1h[N_NODES * D_H];    // relu(agg + b1) half (GEMM2 A)
__device__ __half g_hh2[N_NODES * D_OUT];  // half(dis[i] * (z1@W2)[i])
__device__ float  g_z2[N_NODES * D_OUT];   // agg + b2 (fp32, decode operand)

// ---------------- fused init: weight transpose+convert, zero counts, detect ----------------
__global__ void init_kernel(const float* __restrict__ W1,
                            const float* __restrict__ W2,
                            const int* __restrict__ raw) {
    int i = blockIdx.x * blockDim.x + threadIdx.x;
    if (i < D_IN * D_H) {
        int k = i >> 8, n = i & 255;                 // W1[k][n]
        g_w1t[n * D_IN + k] = __float2half(W1[i]);
    }
    if (i < D_H * D_OUT) {
        int k = i >> 7, n = i & 127;                 // W2[k][n]
        g_w2t[n * D_H + k] = __float2half(W2[i]);
    }
    if (i < N_NODES) g_counts[i] = 0;
    if (blockIdx.x == 0 && threadIdx.x < 32) {
        int nz = 0;
        for (int j = threadIdx.x; j < 256; j += 32)
            nz |= (raw[2 * j + 1] != 0);
        unsigned m = __ballot_sync(0xffffffffu, nz);
        if (threadIdx.x == 0) g_is64 = (m == 0);
    }
}

__global__ void count_kernel(const void* __restrict__ raw, int E) {
    int i = blockIdx.x * blockDim.x + threadIdx.x;
    if (i >= E) return;
    int d;
    if (g_is64) d = (int)((const long long*)raw)[E + i];
    else        d = ((const int*)raw)[E + i];
    atomicAdd(&g_counts[d], 1);
}

// fused: convert x -> half (float4 granular) + dis = rsqrt(deg+1)
__global__ void xconv_dis_kernel(const float* __restrict__ x) {
    int i = blockIdx.x * blockDim.x + threadIdx.x;
    if (i < N_NODES * D_IN / 4) {
        float4 v = ((const float4*)x)[i];
        __half2 h0 = __floats2half2_rn(v.x, v.y);
        __half2 h1 = __floats2half2_rn(v.z, v.w);
        uint2 st; st.x = *(unsigned*)&h0; st.y = *(unsigned*)&h1;
        ((uint2*)g_xh)[i] = st;
    }
    if (i < N_NODES) g_dis[i] = rsqrtf((float)(g_counts[i] + 1));
}

// ---------------- 3-phase parallel exclusive scan ----------------
__global__ __launch_bounds__(1024) void scan_part1(int n) {
    int i = blockIdx.x * 1024 + threadIdx.x;
    int v = (i < n) ? g_counts[i] : 0;
    int lane = threadIdx.x & 31, wid = threadIdx.x >> 5;

    int x = v;
    #pragma unroll
    for (int o = 1; o < 32; o <<= 1) {
        int t = __shfl_up_sync(0xffffffffu, x, o);
        if (lane >= o) x += t;
    }
    __shared__ int wsum[32];
    if (lane == 31) wsum[wid] = x;
    __syncthreads();
    if (wid == 0) {
        int ws = wsum[lane];
        #pragma unroll
        for (int o = 1; o < 32; o <<= 1) {
            int t = __shfl_up_sync(0xffffffffu, ws, o);
            if (lane >= o) ws += t;
        }
        wsum[lane] = ws;
    }
    __syncthreads();
    int incl = x + (wid > 0 ? wsum[wid - 1] : 0);
    if (i < n) g_offsets[i] = incl - v;              // local exclusive
    if (threadIdx.x == 1023) g_bsums[blockIdx.x] = incl;
}

__global__ void scan_part2(int nb, int n) {
    __shared__ int ws[2];
    int lane = threadIdx.x & 31, w = threadIdx.x >> 5;
    int v = (threadIdx.x < nb) ? g_bsums[threadIdx.x] : 0;
    int x = v;
    #pragma unroll
    for (int o = 1; o < 32; o <<= 1) {
        int t = __shfl_up_sync(0xffffffffu, x, o);
        if (lane >= o) x += t;
    }
    if (lane == 31) ws[w] = x;
    __syncthreads();
    int incl = x + ((w == 1) ? ws[0] : 0);
    if (threadIdx.x < nb) g_bsums[threadIdx.x] = incl - v;   // exclusive
    if (threadIdx.x == nb - 1) g_offsets[n] = incl;
}

__global__ __launch_bounds__(1024) void scan_part3(int n) {
    int i = blockIdx.x * 1024 + threadIdx.x;
    if (i < n) {
        int off = g_offsets[i] + g_bsums[blockIdx.x];
        g_offsets[i] = off;
        g_cursor[i]  = off;
    }
}

__global__ void fill_kernel(const void* __restrict__ raw, int E) {
    int i = blockIdx.x * blockDim.x + threadIdx.x;
    if (i >= E) return;
    int s, d;
    if (g_is64) {
        const long long* p = (const long long*)raw;
        s = (int)p[i]; d = (int)p[E + i];
    } else {
        const int* p = (const int*)raw;
        s = p[i]; d = p[E + i];
    }
    int pos = atomicAdd(&g_cursor[d], 1);
    g_src_sorted[pos] = s;
}

// ---------------- fp16 tensor-core GEMM: cp.async double-buffer + ldmatrix ----------------
#define LDH 40                 // padded row (halves): conflict-free for ldmatrix & cp.async
#define BUFH (128 * LDH)       // halves per (A or B) buffer stage

__device__ __forceinline__ void ldmx4(unsigned& r0, unsigned& r1,
                                      unsigned& r2, unsigned& r3, unsigned addr) {
    asm volatile("ldmatrix.sync.aligned.m8n8.x4.shared.b16 {%0,%1,%2,%3}, [%4];"
                 : "=r"(r0), "=r"(r1), "=r"(r2), "=r"(r3) : "r"(addr));
}

__device__ __forceinline__ void cpasync16(unsigned dst, const void* src, int srcsz) {
    asm volatile("cp.async.cg.shared.global [%0], [%1], 16, %2;"
                 :: "r"(dst), "l"(src), "r"(srcsz));
}

__global__ __launch_bounds__(256) void hgemm_kernel(
    const __half* __restrict__ A, const __half* __restrict__ Bt,
    __half* __restrict__ Ch, const float* __restrict__ dis,
    int M, int N, int K)
{
    __shared__ __half As[2][128][LDH];   // [stage][m][k]
    __shared__ __half Bs[2][128][LDH];   // [stage][n][k]

    const int tid  = threadIdx.x;
    const int lane = tid & 31;
    const int w    = tid >> 5;
    const int wm   = (w & 3) * 32;
    const int wn   = (w >> 2) * 64;
    const int bm   = blockIdx.y * 128;
    const int bn   = blockIdx.x * 128;
    const int r    = lane >> 2;
    const int c    = lane & 3;

    float acc[2][8][4];
    #pragma unroll
    for (int i = 0; i < 2; i++)
        #pragma unroll
        for (int j = 0; j < 8; j++)
            #pragma unroll
            for (int q = 0; q < 4; q++) acc[i][j][q] = 0.f;

    const unsigned as_base = (unsigned)__cvta_generic_to_shared(&As[0][0][0]);
    const unsigned bs_base = (unsigned)__cvta_generic_to_shared(&Bs[0][0][0]);

    // chunk mapping: p in {tid, tid+256}; row p>>2, col-chunk (p&3)*8 halves (16B)
    const int r0 = tid >> 2,          cc0 = (tid & 3) * 8;
    const int r1 = (tid + 256) >> 2,  cc1 = ((tid + 256) & 3) * 8;
    const int a0sz = (bm + r0 < M) ? 16 : 0;
    const int a1sz = (bm + r1 < M) ? 16 : 0;
    const unsigned sa0 = (unsigned)((r0 * LDH + cc0) * 2);
    const unsigned sa1 = (unsigned)((r1 * LDH + cc1) * 2);

    const int ntiles = K / 32;

    // ldmatrix per-lane address components
    const int lq = lane >> 3, lr8 = lane & 7;
    const int a_row = (lq & 1) * 8 + lr8;
    const int a_col = (lq >> 1) * 8;
    const int b_row = (lq >> 1) * 8 + lr8;
    const int b_col = (lq & 1) * 8;

    // prologue: issue tile 0 into stage 0
    {
        const int k0 = 0;
        cpasync16(as_base + sa0, A + (long long)(bm + r0) * K + k0 + cc0, a0sz);
        cpasync16(as_base + sa1, A + (long long)(bm + r1) * K + k0 + cc1, a1sz);
        cpasync16(bs_base + sa0, Bt + (long long)(bn + r0) * K + k0 + cc0, 16);
        cpasync16(bs_base + sa1, Bt + (long long)(bn + r1) * K + k0 + cc1, 16);
        asm volatile("cp.async.commit_group;");
    }

    for (int kt = 0; kt < ntiles; kt++) {
        asm volatile("cp.async.wait_group 0;");
        __syncthreads();

        const unsigned buf_off  = (unsigned)((kt & 1) * BUFH * 2);
        // issue next tile into the other stage (its old contents were consumed
        // in iteration kt-1; the sync above ordered that before this write)
        if (kt + 1 < ntiles) {
            const int k0 = (kt + 1) * 32;
            const unsigned nb = (unsigned)(((kt + 1) & 1) * BUFH * 2);
            cpasync16(as_base + nb + sa0, A + (long long)(bm + r0) * K + k0 + cc0, a0sz);
            cpasync16(as_base + nb + sa1, A + (long long)(bm + r1) * K + k0 + cc1, a1sz);
            cpasync16(bs_base + nb + sa0, Bt + (long long)(bn + r0) * K + k0 + cc0, 16);
            cpasync16(bs_base + nb + sa1, Bt + (long long)(bn + r1) * K + k0 + cc1, 16);
            asm volatile("cp.async.commit_group;");
        }

        #pragma unroll
        for (int ks = 0; ks < 2; ks++) {
            int kk = ks * 16;
            unsigned af[2][4];
            #pragma unroll
            for (int tm = 0; tm < 2; tm++) {
                unsigned addr = as_base + buf_off +
                    (unsigned)(((wm + tm * 16 + a_row) * LDH + kk + a_col) * 2);
                ldmx4(af[tm][0], af[tm][1], af[tm][2], af[tm][3], addr);
            }
            unsigned bf[8][2];
            #pragma unroll
            for (int tnp = 0; tnp < 4; tnp++) {
                unsigned addr = bs_base + buf_off +
                    (unsigned)(((wn + tnp * 16 + b_row) * LDH + kk + b_col) * 2);
                ldmx4(bf[2*tnp][0], bf[2*tnp][1],
                      bf[2*tnp+1][0], bf[2*tnp+1][1], addr);
            }
            #pragma unroll
            for (int tm = 0; tm < 2; tm++)
                #pragma unroll
                for (int tn = 0; tn < 8; tn++) {
                    asm volatile(
                        "mma.sync.aligned.m16n8k16.row.col.f32.f16.f16.f32 "
                        "{%0,%1,%2,%3}, {%4,%5,%6,%7}, {%8,%9}, {%0,%1,%2,%3};"
                        : "+f"(acc[tm][tn][0]), "+f"(acc[tm][tn][1]),
                          "+f"(acc[tm][tn][2]), "+f"(acc[tm][tn][3])
                        : "r"(af[tm][0]), "r"(af[tm][1]),
                          "r"(af[tm][2]), "r"(af[tm][3]),
                          "r"(bf[tn][0]), "r"(bf[tn][1]));
                }
        }
    }

    // fused epilogue: scale by dis[row], convert to half
    #pragma unroll
    for (int tm = 0; tm < 2; tm++) {
        int row0 = bm + wm + tm * 16 + r;
        int row1 = row0 + 8;
        float s0 = (row0 < M) ? dis[row0] : 0.f;
        float s1 = (row1 < M) ? dis[row1] : 0.f;
        #pragma unroll
        for (int tn = 0; tn < 8; tn++) {
            int col = bn + wn + tn * 8 + c * 2;
            if (row0 < M) {
                __half2 hv = __floats2half2_rn(acc[tm][tn][0] * s0,
                                               acc[tm][tn][1] * s0);
                *(__half2*)&Ch[(long long)row0 * N + col] = hv;
            }
            if (row1 < M) {
                __half2 hv = __floats2half2_rn(acc[tm][tn][2] * s1,
                                               acc[tm][tn][3] * s1);
                *(__half2*)&Ch[(long long)row1 * N + col] = hv;
            }
        }
    }
}

// ---------------- aggregation (half gathers, pre-scaled) ----------------
template<int D, bool RELU, bool OUT_HALF>
__global__ __launch_bounds__(256) void agg_half_kernel(
    const __half* __restrict__ HH, void* __restrict__ Zout,
    const float* __restrict__ bias)
{
    constexpr int TPN = D / 4;
    constexpr int NPB = 256 / TPN;
    const int node = blockIdx.x * NPB + threadIdx.x / TPN;
    const int t    = threadIdx.x % TPN;
    if (node >= N_NODES) return;

    const float di = g_dis[node];
    const uint2* Hq = (const uint2*)HH;

    uint2 sv = Hq[(long long)node * TPN + t];
    float2 s0 = __half22float2(*(__half2*)&sv.x);
    float2 s1 = __half22float2(*(__half2*)&sv.y);
    float a0 = s0.x, a1 = s0.y, a2 = s1.x, a3 = s1.y;

    int e   = g_offsets[node];
    int end = g_offsets[node + 1];

    for (; e + 4 <= end; e += 4) {
        int n0 = g_src_sorted[e + 0];
        int n1 = g_src_sorted[e + 1];
        int n2 = g_src_sorted[e + 2];
        int n3 = g_src_sorted[e + 3];
        uint2 v0 = Hq[(long long)n0 * TPN + t];
        uint2 v1 = Hq[(long long)n1 * TPN + t];
        uint2 v2 = Hq[(long long)n2 * TPN + t];
        uint2 v3 = Hq[(long long)n3 * TPN + t];
        float2 p;
        p = __half22float2(*(__half2*)&v0.x); a0 += p.x; a1 += p.y;
        p = __half22float2(*(__half2*)&v0.y); a2 += p.x; a3 += p.y;
        p = __half22float2(*(__half2*)&v1.x); a0 += p.x; a1 += p.y;
        p = __half22float2(*(__half2*)&v1.y); a2 += p.x; a3 += p.y;
        p = __half22float2(*(__half2*)&v2.x); a0 += p.x; a1 += p.y;
        p = __half22float2(*(__half2*)&v2.y); a2 += p.x; a3 += p.y;
        p = __half22float2(*(__half2*)&v3.x); a0 += p.x; a1 += p.y;
        p = __half22float2(*(__half2*)&v3.y); a2 += p.x; a3 += p.y;
    }
    for (; e < end; e++) {
        int s = g_src_sorted[e];
        uint2 v = Hq[(long long)s * TPN + t];
        float2 p;
        p = __half22float2(*(__half2*)&v.x); a0 += p.x; a1 += p.y;
        p = __half22float2(*(__half2*)&v.y); a2 += p.x; a3 += p.y;
    }

    const float4 bv = *(const float4*)&bias[t * 4];
    float o0 = a0 * di + bv.x;
    float o1 = a1 * di + bv.y;
    float o2 = a2 * di + bv.z;
    float o3 = a3 * di + bv.w;
    if (RELU) {
        o0 = fmaxf(o0, 0.f); o1 = fmaxf(o1, 0.f);
        o2 = fmaxf(o2, 0.f); o3 = fmaxf(o3, 0.f);
    }
    if (OUT_HALF) {
        __half2 h0 = __floats2half2_rn(o0, o1);
        __half2 h1 = __floats2half2_rn(o2, o3);
        uint2 st; st.x = *(unsigned*)&h0; st.y = *(unsigned*)&h1;
        *(uint2*)&((__half*)Zout)[(long long)node * D + t * 4] = st;
    } else {
        float4 out = make_float4(o0, o1, o2, o3);
        *(float4*)&((float*)Zout)[(long long)node * D + t * 4] = out;
    }
}

// ---------------- decode: y[e] = dot(z2[a], z2[b]) ----------------
__global__ void decode_kernel(const void* __restrict__ eli_raw,
                              const float* __restrict__ Z,
                              float* __restrict__ y, int EL)
{
    int gw   = (blockIdx.x * blockDim.x + threadIdx.x) >> 5;
    int lane = threadIdx.x & 31;
    if (gw >= EL) return;
    int a, b;
    if (g_is64) {
        const long long* p = (const long long*)eli_raw;
        a = (int)p[gw]; b = (int)p[EL + gw];
    } else {
        const int* p = (const int*)eli_raw;
        a = p[gw]; b = p[EL + gw];
    }
    float4 za = *(const float4*)&Z[(long long)a * 128 + lane * 4];
    float4 zb = *(const float4*)&Z[(long long)b * 128 + lane * 4];
    float s = za.x * zb.x + za.y * zb.y + za.z * zb.z + za.w * zb.w;
    #pragma unroll
    for (int o = 16; o; o >>= 1) s += __shfl_down_sync(0xffffffffu, s, o);
    if (lane == 0) y[gw] = s;
}

// ---------------- launch ----------------
extern "C" void kernel_launch(void* const* d_in, const int* in_sizes, int n_in,
                              void* d_out, int out_size)
{
    const float* x   = (const float*)d_in[0];
    const void*  ei  = d_in[1];
    const void*  eli = d_in[2];
    const float* W1  = (const float*)d_in[3];
    const float* b1  = (const float*)d_in[4];
    const float* W2  = (const float*)d_in[5];
    const float* b2  = (const float*)d_in[6];
    float*       y   = (float*)d_out;

    const int E  = in_sizes[1] / 2;
    const int EL = in_sizes[2] / 2;

    __half *xhp, *hh1p, *z1hp, *hh2p, *w1tp, *w2tp;
    float  *z2p, *disp;
    cudaGetSymbolAddress((void**)&xhp,  g_xh);
    cudaGetSymbolAddress((void**)&hh1p, g_hh1);
    cudaGetSymbolAddress((void**)&z1hp, g_z1h);
    cudaGetSymbolAddress((void**)&hh2p, g_hh2);
    cudaGetSymbolAddress((void**)&z2p,  g_z2);
    cudaGetSymbolAddress((void**)&disp, g_dis);
    cudaGetSymbolAddress((void**)&w1tp, g_w1t);
    cudaGetSymbolAddress((void**)&w2tp, g_w2t);

    const int TB = 256;
    // 0: fused init (weights + zero counts + detect)
    init_kernel<<<(D_IN * D_H + TB - 1) / TB, TB>>>(W1, W2, (const int*)ei);
    // 1: degree count
    count_kernel<<<(E + TB - 1) / TB, TB>>>(ei, E);
    // 2: x->half convert + dis
    xconv_dis_kernel<<<(N_NODES * D_IN / 4 + TB - 1) / TB, TB>>>(x);
    // 3: layer-1 GEMM (profiled slot)
    {
        dim3 grid(D_H / 128, (N_NODES + 127) / 128);
        hgemm_kernel<<<grid, 256>>>(xhp, w1tp, hh1p, disp, N_NODES, D_H, D_IN);
    }
    // 4-6: scan
    scan_part1<<<SCAN_B, 1024>>>(N_NODES);
    scan_part2<<<1, 64>>>(SCAN_B, N_NODES);
    scan_part3<<<SCAN_B, 1024>>>(N_NODES);
    // 7: CSR fill
    fill_kernel<<<(E + TB - 1) / TB, TB>>>(ei, E);
    // 8: layer-1 aggregation -> z1 (half)
    agg_half_kernel<D_H, true, true><<<(N_NODES + 3) / 4, 256>>>(hh1p, z1hp, b1);
    // 9: layer-2 GEMM
    {
        dim3 grid(D_OUT / 128, (N_NODES + 127) / 128);
        hgemm_kernel<<<grid, 256>>>(z1hp, w2tp, hh2p, disp, N_NODES, D_OUT, D_H);
    }
    // 10: layer-2 aggregation -> z2 (fp32)
    agg_half_kernel<D_OUT, false, false><<<(N_NODES + 7) / 8, 256>>>(hh2p, z2p, b2);
    // 11: decode
    decode_kernel<<<(EL * 32 + TB - 1) / TB, TB>>>(eli, z2p, y, EL);
}

// round 16
// speedup vs baseline: 1.1903x; 1.0505x over previous
#include <cuda_runtime.h>
#include <cuda_fp16.h>
#include <cstdint>

#define N_NODES 50000
#define D_IN    256
#define D_H     256
#define D_OUT   128
#define MAX_E   1600000
#define MAX_EL  100000
#define SCAN_B  49          // ceil(50000/1024)

// ---------------- scratch (device globals; no allocation) ----------------
__device__ int    g_is64;
__device__ int    g_counts[N_NODES];
__device__ int    g_offsets[N_NODES + 1];
__device__ int    g_cursor[N_NODES];
__device__ int    g_bsums[64];
__device__ float  g_dis[N_NODES];
__device__ int    g_src_sorted[MAX_E];
__device__ __half g_xh[N_NODES * D_IN];    // half(x)
__device__ __half g_w1t[D_H * D_IN];       // W1^T [n][k] half
__device__ __half g_w2t[D_OUT * D_H];      // W2^T [n][k] half
__device__ __half g_hh1[N_NODES * D_H];    // half(dis[i] * (x@W1)[i])
__device__ __half g_z1h[N_NODES * D_H];    // relu(agg + b1) half (GEMM2 A)
__device__ __half g_hh2[N_NODES * D_OUT];  // half(dis[i] * (z1@W2)[i])
__device__ float  g_z2[N_NODES * D_OUT];   // agg + b2 (fp32, decode operand)

// ---------------- fused init: weight transpose+convert, zero counts, detect ----------------
__global__ void init_kernel(const float* __restrict__ W1,
                            const float* __restrict__ W2,
                            const int* __restrict__ raw) {
    int i = blockIdx.x * blockDim.x + threadIdx.x;
    if (i < D_IN * D_H) {
        int k = i >> 8, n = i & 255;                 // W1[k][n]
        g_w1t[n * D_IN + k] = __float2half(W1[i]);
    }
    if (i < D_H * D_OUT) {
        int k = i >> 7, n = i & 127;                 // W2[k][n]
        g_w2t[n * D_H + k] = __float2half(W2[i]);
    }
    if (i < N_NODES) g_counts[i] = 0;
    if (blockIdx.x == 0 && threadIdx.x < 32) {
        int nz = 0;
        for (int j = threadIdx.x; j < 256; j += 32)
            nz |= (raw[2 * j + 1] != 0);
        unsigned m = __ballot_sync(0xffffffffu, nz);
        if (threadIdx.x == 0) g_is64 = (m == 0);
    }
}

__global__ void count_kernel(const void* __restrict__ raw, int E) {
    int i = blockIdx.x * blockDim.x + threadIdx.x;
    if (i >= E) return;
    int d;
    if (g_is64) d = (int)((const long long*)raw)[E + i];
    else        d = ((const int*)raw)[E + i];
    atomicAdd(&g_counts[d], 1);
}

// fused: convert x -> half (float4 granular) + dis = rsqrt(deg+1)
__global__ void xconv_dis_kernel(const float* __restrict__ x) {
    int i = blockIdx.x * blockDim.x + threadIdx.x;
    if (i < N_NODES * D_IN / 4) {
        float4 v = ((const float4*)x)[i];
        __half2 h0 = __floats2half2_rn(v.x, v.y);
        __half2 h1 = __floats2half2_rn(v.z, v.w);
        uint2 st; st.x = *(unsigned*)&h0; st.y = *(unsigned*)&h1;
        ((uint2*)g_xh)[i] = st;
    }
    if (i < N_NODES) g_dis[i] = rsqrtf((float)(g_counts[i] + 1));
}

// ---------------- 3-phase parallel exclusive scan ----------------
__global__ __launch_bounds__(1024) void scan_part1(int n) {
    int i = blockIdx.x * 1024 + threadIdx.x;
    int v = (i < n) ? g_counts[i] : 0;
    int lane = threadIdx.x & 31, wid = threadIdx.x >> 5;

    int x = v;
    #pragma unroll
    for (int o = 1; o < 32; o <<= 1) {
        int t = __shfl_up_sync(0xffffffffu, x, o);
        if (lane >= o) x += t;
    }
    __shared__ int wsum[32];
    if (lane == 31) wsum[wid] = x;
    __syncthreads();
    if (wid == 0) {
        int ws = wsum[lane];
        #pragma unroll
        for (int o = 1; o < 32; o <<= 1) {
            int t = __shfl_up_sync(0xffffffffu, ws, o);
            if (lane >= o) ws += t;
        }
        wsum[lane] = ws;
    }
    __syncthreads();
    int incl = x + (wid > 0 ? wsum[wid - 1] : 0);
    if (i < n) g_offsets[i] = incl - v;              // local exclusive
    if (threadIdx.x == 1023) g_bsums[blockIdx.x] = incl;
}

__global__ void scan_part2(int nb, int n) {
    __shared__ int ws[2];
    int lane = threadIdx.x & 31, w = threadIdx.x >> 5;
    int v = (threadIdx.x < nb) ? g_bsums[threadIdx.x] : 0;
    int x = v;
    #pragma unroll
    for (int o = 1; o < 32; o <<= 1) {
        int t = __shfl_up_sync(0xffffffffu, x, o);
        if (lane >= o) x += t;
    }
    if (lane == 31) ws[w] = x;
    __syncthreads();
    int incl = x + ((w == 1) ? ws[0] : 0);
    if (threadIdx.x < nb) g_bsums[threadIdx.x] = incl - v;   // exclusive
    if (threadIdx.x == nb - 1) g_offsets[n] = incl;
}

__global__ __launch_bounds__(1024) void scan_part3(int n) {
    int i = blockIdx.x * 1024 + threadIdx.x;
    if (i < n) {
        int off = g_offsets[i] + g_bsums[blockIdx.x];
        g_offsets[i] = off;
        g_cursor[i]  = off;
    }
}

__global__ void fill_kernel(const void* __restrict__ raw, int E) {
    int i = blockIdx.x * blockDim.x + threadIdx.x;
    if (i >= E) return;
    int s, d;
    if (g_is64) {
        const long long* p = (const long long*)raw;
        s = (int)p[i]; d = (int)p[E + i];
    } else {
        const int* p = (const int*)raw;
        s = p[i]; d = p[E + i];
    }
    int pos = atomicAdd(&g_cursor[d], 1);
    g_src_sorted[pos] = s;
}

// ---------------- fp16 tensor-core GEMM: cp.async double-buffer + ldmatrix ----------------
#define LDH 40                 // padded row (halves): conflict-free for ldmatrix & cp.async
#define BUFH (128 * LDH)       // halves per (A or B) buffer stage

__device__ __forceinline__ void ldmx4(unsigned& r0, unsigned& r1,
                                      unsigned& r2, unsigned& r3, unsigned addr) {
    asm volatile("ldmatrix.sync.aligned.m8n8.x4.shared.b16 {%0,%1,%2,%3}, [%4];"
                 : "=r"(r0), "=r"(r1), "=r"(r2), "=r"(r3) : "r"(addr));
}

__device__ __forceinline__ void cpasync16(unsigned dst, const void* src, int srcsz) {
    asm volatile("cp.async.cg.shared.global [%0], [%1], 16, %2;"
                 :: "r"(dst), "l"(src), "r"(srcsz));
}

__global__ __launch_bounds__(256) void hgemm_kernel(
    const __half* __restrict__ A, const __half* __restrict__ Bt,
    __half* __restrict__ Ch, const float* __restrict__ dis,
    int M, int N, int K)
{
    __shared__ __half As[2][128][LDH];   // [stage][m][k]
    __shared__ __half Bs[2][128][LDH];   // [stage][n][k]

    const int tid  = threadIdx.x;
    const int lane = tid & 31;
    const int w    = tid >> 5;
    const int wm   = (w & 3) * 32;
    const int wn   = (w >> 2) * 64;
    const int bm   = blockIdx.y * 128;
    const int bn   = blockIdx.x * 128;
    const int r    = lane >> 2;
    const int c    = lane & 3;

    float acc[2][8][4];
    #pragma unroll
    for (int i = 0; i < 2; i++)
        #pragma unroll
        for (int j = 0; j < 8; j++)
            #pragma unroll
            for (int q = 0; q < 4; q++) acc[i][j][q] = 0.f;

    const unsigned as_base = (unsigned)__cvta_generic_to_shared(&As[0][0][0]);
    const unsigned bs_base = (unsigned)__cvta_generic_to_shared(&Bs[0][0][0]);

    // chunk mapping: p in {tid, tid+256}; row p>>2, col-chunk (p&3)*8 halves (16B)
    const int r0 = tid >> 2,          cc0 = (tid & 3) * 8;
    const int r1 = (tid + 256) >> 2,  cc1 = ((tid + 256) & 3) * 8;
    const int a0sz = (bm + r0 < M) ? 16 : 0;
    const int a1sz = (bm + r1 < M) ? 16 : 0;
    const unsigned sa0 = (unsigned)((r0 * LDH + cc0) * 2);
    const unsigned sa1 = (unsigned)((r1 * LDH + cc1) * 2);

    const int ntiles = K / 32;

    // ldmatrix per-lane address components
    const int lq = lane >> 3, lr8 = lane & 7;
    const int a_row = (lq & 1) * 8 + lr8;
    const int a_col = (lq >> 1) * 8;
    const int b_row = (lq >> 1) * 8 + lr8;
    const int b_col = (lq & 1) * 8;

    // prologue: issue tile 0 into stage 0
    {
        const int k0 = 0;
        cpasync16(as_base + sa0, A + (long long)(bm + r0) * K + k0 + cc0, a0sz);
        cpasync16(as_base + sa1, A + (long long)(bm + r1) * K + k0 + cc1, a1sz);
        cpasync16(bs_base + sa0, Bt + (long long)(bn + r0) * K + k0 + cc0, 16);
        cpasync16(bs_base + sa1, Bt + (long long)(bn + r1) * K + k0 + cc1, 16);
        asm volatile("cp.async.commit_group;");
    }

    for (int kt = 0; kt < ntiles; kt++) {
        asm volatile("cp.async.wait_group 0;");
        __syncthreads();

        const unsigned buf_off  = (unsigned)((kt & 1) * BUFH * 2);
        if (kt + 1 < ntiles) {
            const int k0 = (kt + 1) * 32;
            const unsigned nb = (unsigned)(((kt + 1) & 1) * BUFH * 2);
            cpasync16(as_base + nb + sa0, A + (long long)(bm + r0) * K + k0 + cc0, a0sz);
            cpasync16(as_base + nb + sa1, A + (long long)(bm + r1) * K + k0 + cc1, a1sz);
            cpasync16(bs_base + nb + sa0, Bt + (long long)(bn + r0) * K + k0 + cc0, 16);
            cpasync16(bs_base + nb + sa1, Bt + (long long)(bn + r1) * K + k0 + cc1, 16);
            asm volatile("cp.async.commit_group;");
        }

        #pragma unroll
        for (int ks = 0; ks < 2; ks++) {
            int kk = ks * 16;
            unsigned af[2][4];
            #pragma unroll
            for (int tm = 0; tm < 2; tm++) {
                unsigned addr = as_base + buf_off +
                    (unsigned)(((wm + tm * 16 + a_row) * LDH + kk + a_col) * 2);
                ldmx4(af[tm][0], af[tm][1], af[tm][2], af[tm][3], addr);
            }
            unsigned bf[8][2];
            #pragma unroll
            for (int tnp = 0; tnp < 4; tnp++) {
                unsigned addr = bs_base + buf_off +
                    (unsigned)(((wn + tnp * 16 + b_row) * LDH + kk + b_col) * 2);
                ldmx4(bf[2*tnp][0], bf[2*tnp][1],
                      bf[2*tnp+1][0], bf[2*tnp+1][1], addr);
            }
            #pragma unroll
            for (int tm = 0; tm < 2; tm++)
                #pragma unroll
                for (int tn = 0; tn < 8; tn++) {
                    asm volatile(
                        "mma.sync.aligned.m16n8k16.row.col.f32.f16.f16.f32 "
                        "{%0,%1,%2,%3}, {%4,%5,%6,%7}, {%8,%9}, {%0,%1,%2,%3};"
                        : "+f"(acc[tm][tn][0]), "+f"(acc[tm][tn][1]),
                          "+f"(acc[tm][tn][2]), "+f"(acc[tm][tn][3])
                        : "r"(af[tm][0]), "r"(af[tm][1]),
                          "r"(af[tm][2]), "r"(af[tm][3]),
                          "r"(bf[tn][0]), "r"(bf[tn][1]));
                }
        }
    }

    // fused epilogue: scale by dis[row], convert to half
    #pragma unroll
    for (int tm = 0; tm < 2; tm++) {
        int row0 = bm + wm + tm * 16 + r;
        int row1 = row0 + 8;
        float s0 = (row0 < M) ? dis[row0] : 0.f;
        float s1 = (row1 < M) ? dis[row1] : 0.f;
        #pragma unroll
        for (int tn = 0; tn < 8; tn++) {
            int col = bn + wn + tn * 8 + c * 2;
            if (row0 < M) {
                __half2 hv = __floats2half2_rn(acc[tm][tn][0] * s0,
                                               acc[tm][tn][1] * s0);
                *(__half2*)&Ch[(long long)row0 * N + col] = hv;
            }
            if (row1 < M) {
                __half2 hv = __floats2half2_rn(acc[tm][tn][2] * s1,
                                               acc[tm][tn][3] * s1);
                *(__half2*)&Ch[(long long)row1 * N + col] = hv;
            }
        }
    }
}

// ---------------- aggregation: warp per node, wide gathers ----------------
// z[i] = f( di * ( hh[i] + sum_{s in N(i)} hh[s] ) + b )   where hh = h*dis
// D=256: VEC=8 halves/thread (uint4).  D=128: VEC=4 halves/thread (uint2).
template<int D, bool RELU, bool OUT_HALF>
__global__ __launch_bounds__(256) void agg_warp_kernel(
    const __half* __restrict__ HH, void* __restrict__ Zout,
    const float* __restrict__ bias)
{
    constexpr int VEC = D / 32;          // halves per thread: 8 or 4
    const int wid  = threadIdx.x >> 5;
    const int lane = threadIdx.x & 31;
    const int node = blockIdx.x * 8 + wid;
    if (node >= N_NODES) return;

    const float di = g_dis[node];
    float acc[VEC];

    const __half* selfrow = HH + (long long)node * D + lane * VEC;
    if (VEC == 8) {
        uint4 v = *(const uint4*)selfrow;
        const __half2* h = (const __half2*)&v;
        #pragma unroll
        for (int j = 0; j < 4; j++) {
            float2 p = __half22float2(h[j]);
            acc[2*j] = p.x; acc[2*j+1] = p.y;
        }
    } else {
        uint2 v = *(const uint2*)selfrow;
        const __half2* h = (const __half2*)&v;
        #pragma unroll
        for (int j = 0; j < 2; j++) {
            float2 p = __half22float2(h[j]);
            acc[2*j] = p.x; acc[2*j+1] = p.y;
        }
    }

    int e   = g_offsets[node];
    int end = g_offsets[node + 1];

    for (; e + 4 <= end; e += 4) {
        int n0 = g_src_sorted[e + 0];
        int n1 = g_src_sorted[e + 1];
        int n2 = g_src_sorted[e + 2];
        int n3 = g_src_sorted[e + 3];
        if (VEC == 8) {
            uint4 v0 = *(const uint4*)(HH + (long long)n0 * D + lane * VEC);
            uint4 v1 = *(const uint4*)(HH + (long long)n1 * D + lane * VEC);
            uint4 v2 = *(const uint4*)(HH + (long long)n2 * D + lane * VEC);
            uint4 v3 = *(const uint4*)(HH + (long long)n3 * D + lane * VEC);
            const __half2* h0 = (const __half2*)&v0;
            const __half2* h1 = (const __half2*)&v1;
            const __half2* h2 = (const __half2*)&v2;
            const __half2* h3 = (const __half2*)&v3;
            #pragma unroll
            for (int j = 0; j < 4; j++) {
                float2 p;
                p = __half22float2(h0[j]); acc[2*j] += p.x; acc[2*j+1] += p.y;
                p = __half22float2(h1[j]); acc[2*j] += p.x; acc[2*j+1] += p.y;
                p = __half22float2(h2[j]); acc[2*j] += p.x; acc[2*j+1] += p.y;
                p = __half22float2(h3[j]); acc[2*j] += p.x; acc[2*j+1] += p.y;
            }
        } else {
            uint2 v0 = *(const uint2*)(HH + (long long)n0 * D + lane * VEC);
            uint2 v1 = *(const uint2*)(HH + (long long)n1 * D + lane * VEC);
            uint2 v2 = *(const uint2*)(HH + (long long)n2 * D + lane * VEC);
            uint2 v3 = *(const uint2*)(HH + (long long)n3 * D + lane * VEC);
            const __half2* h0 = (const __half2*)&v0;
            const __half2* h1 = (const __half2*)&v1;
            const __half2* h2 = (const __half2*)&v2;
            const __half2* h3 = (const __half2*)&v3;
            #pragma unroll
            for (int j = 0; j < 2; j++) {
                float2 p;
                p = __half22float2(h0[j]); acc[2*j] += p.x; acc[2*j+1] += p.y;
                p = __half22float2(h1[j]); acc[2*j] += p.x; acc[2*j+1] += p.y;
                p = __half22float2(h2[j]); acc[2*j] += p.x; acc[2*j+1] += p.y;
                p = __half22float2(h3[j]); acc[2*j] += p.x; acc[2*j+1] += p.y;
            }
        }
    }
    for (; e < end; e++) {
        int s = g_src_sorted[e];
        if (VEC == 8) {
            uint4 v = *(const uint4*)(HH + (long long)s * D + lane * VEC);
            const __half2* h = (const __half2*)&v;
            #pragma unroll
            for (int j = 0; j < 4; j++) {
                float2 p = __half22float2(h[j]);
                acc[2*j] += p.x; acc[2*j+1] += p.y;
            }
        } else {
            uint2 v = *(const uint2*)(HH + (long long)s * D + lane * VEC);
            const __half2* h = (const __half2*)&v;
            #pragma unroll
            for (int j = 0; j < 2; j++) {
                float2 p = __half22float2(h[j]);
                acc[2*j] += p.x; acc[2*j+1] += p.y;
            }
        }
    }

    // finalize: o = acc*di + bias, optional relu, store
    float o[VEC];
    #pragma unroll
    for (int j = 0; j < VEC; j++) {
        o[j] = acc[j] * di + bias[lane * VEC + j];
        if (RELU) o[j] = fmaxf(o[j], 0.f);
    }
    if (OUT_HALF) {
        __half* zp = (__half*)Zout + (long long)node * D + lane * VEC;
        if (VEC == 8) {
            __half2 h[4];
            #pragma unroll
            for (int j = 0; j < 4; j++) h[j] = __floats2half2_rn(o[2*j], o[2*j+1]);
            *(uint4*)zp = *(uint4*)h;
        } else {
            __half2 h[2];
            #pragma unroll
            for (int j = 0; j < 2; j++) h[j] = __floats2half2_rn(o[2*j], o[2*j+1]);
            *(uint2*)zp = *(uint2*)h;
        }
    } else {
        float* zp = (float*)Zout + (long long)node * D + lane * VEC;
        #pragma unroll
        for (int j = 0; j < VEC; j += 4)
            *(float4*)&zp[j] = make_float4(o[j], o[j+1], o[j+2], o[j+3]);
    }
}

// ---------------- decode: y[e] = dot(z2[a], z2[b]) ----------------
__global__ void decode_kernel(const void* __restrict__ eli_raw,
                              const float* __restrict__ Z,
                              float* __restrict__ y, int EL)
{
    int gw   = (blockIdx.x * blockDim.x + threadIdx.x) >> 5;
    int lane = threadIdx.x & 31;
    if (gw >= EL) return;
    int a, b;
    if (g_is64) {
        const long long* p = (const long long*)eli_raw;
        a = (int)p[gw]; b = (int)p[EL + gw];
    } else {
        const int* p = (const int*)eli_raw;
        a = p[gw]; b = p[EL + gw];
    }
    float4 za = *(const float4*)&Z[(long long)a * 128 + lane * 4];
    float4 zb = *(const float4*)&Z[(long long)b * 128 + lane * 4];
    float s = za.x * zb.x + za.y * zb.y + za.z * zb.z + za.w * zb.w;
    #pragma unroll
    for (int o = 16; o; o >>= 1) s += __shfl_down_sync(0xffffffffu, s, o);
    if (lane == 0) y[gw] = s;
}

// ---------------- launch ----------------
extern "C" void kernel_launch(void* const* d_in, const int* in_sizes, int n_in,
                              void* d_out, int out_size)
{
    const float* x   = (const float*)d_in[0];
    const void*  ei  = d_in[1];
    const void*  eli = d_in[2];
    const float* W1  = (const float*)d_in[3];
    const float* b1  = (const float*)d_in[4];
    const float* W2  = (const float*)d_in[5];
    const float* b2  = (const float*)d_in[6];
    float*       y   = (float*)d_out;

    const int E  = in_sizes[1] / 2;
    const int EL = in_sizes[2] / 2;

    __half *xhp, *hh1p, *z1hp, *hh2p, *w1tp, *w2tp;
    float  *z2p, *disp;
    cudaGetSymbolAddress((void**)&xhp,  g_xh);
    cudaGetSymbolAddress((void**)&hh1p, g_hh1);
    cudaGetSymbolAddress((void**)&z1hp, g_z1h);
    cudaGetSymbolAddress((void**)&hh2p, g_hh2);
    cudaGetSymbolAddress((void**)&z2p,  g_z2);
    cudaGetSymbolAddress((void**)&disp, g_dis);
    cudaGetSymbolAddress((void**)&w1tp, g_w1t);
    cudaGetSymbolAddress((void**)&w2tp, g_w2t);

    const int TB = 256;
    // 0: fused init (weights + zero counts + detect)
    init_kernel<<<(D_IN * D_H + TB - 1) / TB, TB>>>(W1, W2, (const int*)ei);
    // 1: degree count
    count_kernel<<<(E + TB - 1) / TB, TB>>>(ei, E);
    // 2: x->half convert + dis
    xconv_dis_kernel<<<(N_NODES * D_IN / 4 + TB - 1) / TB, TB>>>(x);
    // 3: layer-1 GEMM (profiled slot)
    {
        dim3 grid(D_H / 128, (N_NODES + 127) / 128);
        hgemm_kernel<<<grid, 256>>>(xhp, w1tp, hh1p, disp, N_NODES, D_H, D_IN);
    }
    // 4-6: scan
    scan_part1<<<SCAN_B, 1024>>>(N_NODES);
    scan_part2<<<1, 64>>>(SCAN_B, N_NODES);
    scan_part3<<<SCAN_B, 1024>>>(N_NODES);
    // 7: CSR fill
    fill_kernel<<<(E + TB - 1) / TB, TB>>>(ei, E);
    // 8: layer-1 aggregation -> z1 (half)
    agg_warp_kernel<D_H, true, true><<<(N_NODES + 7) / 8, 256>>>(hh1p, z1hp, b1);
    // 9: layer-2 GEMM
    {
        dim3 grid(D_OUT / 128, (N_NODES + 127) / 128);
        hgemm_kernel<<<grid, 256>>>(z1hp, w2tp, hh2p, disp, N_NODES, D_OUT, D_H);
    }
    // 10: layer-2 aggregation -> z2 (fp32)
    agg_warp_kernel<D_OUT, false, false><<<(N_NODES + 7) / 8, 256>>>(hh2p, z2p, b2);
    // 11: decode
    decode_kernel<<<(EL * 32 + TB - 1) / TB, TB>>>(eli, z2p, y, EL);
}

// round 17
// speedup vs baseline: 1.2799x; 1.0753x over previous
#include <cuda_runtime.h>
#include <cuda_fp16.h>
#include <cstdint>

#define N_NODES 50000
#define D_IN    256
#define D_H     256
#define D_OUT   128
#define MAX_E   1600000
#define MAX_EL  100000
#define SCAN_B  49          // ceil(50000/1024)

// ---------------- scratch (device globals; no allocation) ----------------
__device__ int    g_is64;
__device__ int    g_counts[N_NODES];
__device__ int    g_offsets[N_NODES + 1];
__device__ int    g_cursor[N_NODES];
__device__ int    g_bsums[64];
__device__ float  g_dis[N_NODES];
__device__ int    g_src_sorted[MAX_E];
__device__ __half g_xh[N_NODES * D_IN];    // half(x)
__device__ __half g_w1t[D_H * D_IN];       // W1^T [n][k] half
__device__ __half g_w2t[D_OUT * D_H];      // W2^T [n][k] half
__device__ __half g_hh1[N_NODES * D_H];    // half(dis[i] * (x@W1)[i])
__device__ __half g_z1h[N_NODES * D_H];    // relu(agg + b1) half (GEMM2 A)
__device__ __half g_hh2[N_NODES * D_OUT];  // half(dis[i] * (z1@W2)[i])
__device__ float  g_z2[N_NODES * D_OUT];   // agg + b2 (fp32, decode operand)

// ---------------- fused init: weight transpose+convert, zero counts, detect ----------------
__global__ void init_kernel(const float* __restrict__ W1,
                            const float* __restrict__ W2,
                            const int* __restrict__ raw) {
    int i = blockIdx.x * blockDim.x + threadIdx.x;
    if (i < D_IN * D_H) {
        int k = i >> 8, n = i & 255;                 // W1[k][n]
        g_w1t[n * D_IN + k] = __float2half(W1[i]);
    }
    if (i < D_H * D_OUT) {
        int k = i >> 7, n = i & 127;                 // W2[k][n]
        g_w2t[n * D_H + k] = __float2half(W2[i]);
    }
    if (i < N_NODES) g_counts[i] = 0;
    if (blockIdx.x == 0 && threadIdx.x < 32) {
        int nz = 0;
        for (int j = threadIdx.x; j < 256; j += 32)
            nz |= (raw[2 * j + 1] != 0);
        unsigned m = __ballot_sync(0xffffffffu, nz);
        if (threadIdx.x == 0) g_is64 = (m == 0);
    }
}

__global__ void count_kernel(const void* __restrict__ raw, int E) {
    int i = blockIdx.x * blockDim.x + threadIdx.x;
    if (i >= E) return;
    int d;
    if (g_is64) d = (int)((const long long*)raw)[E + i];
    else        d = ((const int*)raw)[E + i];
    atomicAdd(&g_counts[d], 1);
}

// x -> half (float4 granular); independent of graph prep (runs on side stream)
__global__ void xconv_kernel(const float* __restrict__ x) {
    int i = blockIdx.x * blockDim.x + threadIdx.x;
    if (i < N_NODES * D_IN / 4) {
        float4 v = ((const float4*)x)[i];
        __half2 h0 = __floats2half2_rn(v.x, v.y);
        __half2 h1 = __floats2half2_rn(v.z, v.w);
        uint2 st; st.x = *(unsigned*)&h0; st.y = *(unsigned*)&h1;
        ((uint2*)g_xh)[i] = st;
    }
}

__global__ void dis_kernel() {
    int i = blockIdx.x * blockDim.x + threadIdx.x;
    if (i < N_NODES) g_dis[i] = rsqrtf((float)(g_counts[i] + 1));
}

// ---------------- 3-phase parallel exclusive scan ----------------
__global__ __launch_bounds__(1024) void scan_part1(int n) {
    int i = blockIdx.x * 1024 + threadIdx.x;
    int v = (i < n) ? g_counts[i] : 0;
    int lane = threadIdx.x & 31, wid = threadIdx.x >> 5;

    int x = v;
    #pragma unroll
    for (int o = 1; o < 32; o <<= 1) {
        int t = __shfl_up_sync(0xffffffffu, x, o);
        if (lane >= o) x += t;
    }
    __shared__ int wsum[32];
    if (lane == 31) wsum[wid] = x;
    __syncthreads();
    if (wid == 0) {
        int ws = wsum[lane];
        #pragma unroll
        for (int o = 1; o < 32; o <<= 1) {
            int t = __shfl_up_sync(0xffffffffu, ws, o);
            if (lane >= o) ws += t;
        }
        wsum[lane] = ws;
    }
    __syncthreads();
    int incl = x + (wid > 0 ? wsum[wid - 1] : 0);
    if (i < n) g_offsets[i] = incl - v;              // local exclusive
    if (threadIdx.x == 1023) g_bsums[blockIdx.x] = incl;
}

__global__ void scan_part2(int nb, int n) {
    __shared__ int ws[2];
    int lane = threadIdx.x & 31, w = threadIdx.x >> 5;
    int v = (threadIdx.x < nb) ? g_bsums[threadIdx.x] : 0;
    int x = v;
    #pragma unroll
    for (int o = 1; o < 32; o <<= 1) {
        int t = __shfl_up_sync(0xffffffffu, x, o);
        if (lane >= o) x += t;
    }
    if (lane == 31) ws[w] = x;
    __syncthreads();
    int incl = x + ((w == 1) ? ws[0] : 0);
    if (threadIdx.x < nb) g_bsums[threadIdx.x] = incl - v;   // exclusive
    if (threadIdx.x == nb - 1) g_offsets[n] = incl;
}

__global__ __launch_bounds__(1024) void scan_part3(int n) {
    int i = blockIdx.x * 1024 + threadIdx.x;
    if (i < n) {
        int off = g_offsets[i] + g_bsums[blockIdx.x];
        g_offsets[i] = off;
        g_cursor[i]  = off;
    }
}

__global__ void fill_kernel(const void* __restrict__ raw, int E) {
    int i = blockIdx.x * blockDim.x + threadIdx.x;
    if (i >= E) return;
    int s, d;
    if (g_is64) {
        const long long* p = (const long long*)raw;
        s = (int)p[i]; d = (int)p[E + i];
    } else {
        const int* p = (const int*)raw;
        s = p[i]; d = p[E + i];
    }
    int pos = atomicAdd(&g_cursor[d], 1);
    g_src_sorted[pos] = s;
}

// ---------------- fp16 tensor-core GEMM: cp.async double-buffer + ldmatrix ----------------
#define LDH 40                 // padded row (halves): conflict-free for ldmatrix & cp.async
#define BUFH (128 * LDH)       // halves per (A or B) buffer stage

__device__ __forceinline__ void ldmx4(unsigned& r0, unsigned& r1,
                                      unsigned& r2, unsigned& r3, unsigned addr) {
    asm volatile("ldmatrix.sync.aligned.m8n8.x4.shared.b16 {%0,%1,%2,%3}, [%4];"
                 : "=r"(r0), "=r"(r1), "=r"(r2), "=r"(r3) : "r"(addr));
}

__device__ __forceinline__ void cpasync16(unsigned dst, const void* src, int srcsz) {
    asm volatile("cp.async.cg.shared.global [%0], [%1], 16, %2;"
                 :: "r"(dst), "l"(src), "r"(srcsz));
}

__global__ __launch_bounds__(256) void hgemm_kernel(
    const __half* __restrict__ A, const __half* __restrict__ Bt,
    __half* __restrict__ Ch, const float* __restrict__ dis,
    int M, int N, int K)
{
    __shared__ __half As[2][128][LDH];   // [stage][m][k]
    __shared__ __half Bs[2][128][LDH];   // [stage][n][k]

    const int tid  = threadIdx.x;
    const int lane = tid & 31;
    const int w    = tid >> 5;
    const int wm   = (w & 3) * 32;
    const int wn   = (w >> 2) * 64;
    const int bm   = blockIdx.y * 128;
    const int bn   = blockIdx.x * 128;
    const int r    = lane >> 2;
    const int c    = lane & 3;

    float acc[2][8][4];
    #pragma unroll
    for (int i = 0; i < 2; i++)
        #pragma unroll
        for (int j = 0; j < 8; j++)
            #pragma unroll
            for (int q = 0; q < 4; q++) acc[i][j][q] = 0.f;

    const unsigned as_base = (unsigned)__cvta_generic_to_shared(&As[0][0][0]);
    const unsigned bs_base = (unsigned)__cvta_generic_to_shared(&Bs[0][0][0]);

    // chunk mapping: p in {tid, tid+256}; row p>>2, col-chunk (p&3)*8 halves (16B)
    const int r0 = tid >> 2,          cc0 = (tid & 3) * 8;
    const int r1 = (tid + 256) >> 2,  cc1 = ((tid + 256) & 3) * 8;
    const int a0sz = (bm + r0 < M) ? 16 : 0;
    const int a1sz = (bm + r1 < M) ? 16 : 0;
    const unsigned sa0 = (unsigned)((r0 * LDH + cc0) * 2);
    const unsigned sa1 = (unsigned)((r1 * LDH + cc1) * 2);

    const int ntiles = K / 32;

    // ldmatrix per-lane address components
    const int lq = lane >> 3, lr8 = lane & 7;
    const int a_row = (lq & 1) * 8 + lr8;
    const int a_col = (lq >> 1) * 8;
    const int b_row = (lq >> 1) * 8 + lr8;
    const int b_col = (lq & 1) * 8;

    // prologue: issue tile 0 into stage 0
    {
        const int k0 = 0;
        cpasync16(as_base + sa0, A + (long long)(bm + r0) * K + k0 + cc0, a0sz);
        cpasync16(as_base + sa1, A + (long long)(bm + r1) * K + k0 + cc1, a1sz);
        cpasync16(bs_base + sa0, Bt + (long long)(bn + r0) * K + k0 + cc0, 16);
        cpasync16(bs_base + sa1, Bt + (long long)(bn + r1) * K + k0 + cc1, 16);
        asm volatile("cp.async.commit_group;");
    }

    for (int kt = 0; kt < ntiles; kt++) {
        asm volatile("cp.async.wait_group 0;");
        __syncthreads();

        const unsigned buf_off  = (unsigned)((kt & 1) * BUFH * 2);
        if (kt + 1 < ntiles) {
            const int k0 = (kt + 1) * 32;
            const unsigned nb = (unsigned)(((kt + 1) & 1) * BUFH * 2);
            cpasync16(as_base + nb + sa0, A + (long long)(bm + r0) * K + k0 + cc0, a0sz);
            cpasync16(as_base + nb + sa1, A + (long long)(bm + r1) * K + k0 + cc1, a1sz);
            cpasync16(bs_base + nb + sa0, Bt + (long long)(bn + r0) * K + k0 + cc0, 16);
            cpasync16(bs_base + nb + sa1, Bt + (long long)(bn + r1) * K + k0 + cc1, 16);
            asm volatile("cp.async.commit_group;");
        }

        #pragma unroll
        for (int ks = 0; ks < 2; ks++) {
            int kk = ks * 16;
            unsigned af[2][4];
            #pragma unroll
            for (int tm = 0; tm < 2; tm++) {
                unsigned addr = as_base + buf_off +
                    (unsigned)(((wm + tm * 16 + a_row) * LDH + kk + a_col) * 2);
                ldmx4(af[tm][0], af[tm][1], af[tm][2], af[tm][3], addr);
            }
            unsigned bf[8][2];
            #pragma unroll
            for (int tnp = 0; tnp < 4; tnp++) {
                unsigned addr = bs_base + buf_off +
                    (unsigned)(((wn + tnp * 16 + b_row) * LDH + kk + b_col) * 2);
                ldmx4(bf[2*tnp][0], bf[2*tnp][1],
                      bf[2*tnp+1][0], bf[2*tnp+1][1], addr);
            }
            #pragma unroll
            for (int tm = 0; tm < 2; tm++)
                #pragma unroll
                for (int tn = 0; tn < 8; tn++) {
                    asm volatile(
                        "mma.sync.aligned.m16n8k16.row.col.f32.f16.f16.f32 "
                        "{%0,%1,%2,%3}, {%4,%5,%6,%7}, {%8,%9}, {%0,%1,%2,%3};"
                        : "+f"(acc[tm][tn][0]), "+f"(acc[tm][tn][1]),
                          "+f"(acc[tm][tn][2]), "+f"(acc[tm][tn][3])
                        : "r"(af[tm][0]), "r"(af[tm][1]),
                          "r"(af[tm][2]), "r"(af[tm][3]),
                          "r"(bf[tn][0]), "r"(bf[tn][1]));
                }
        }
    }

    // fused epilogue: scale by dis[row], convert to half
    #pragma unroll
    for (int tm = 0; tm < 2; tm++) {
        int row0 = bm + wm + tm * 16 + r;
        int row1 = row0 + 8;
        float s0 = (row0 < M) ? dis[row0] : 0.f;
        float s1 = (row1 < M) ? dis[row1] : 0.f;
        #pragma unroll
        for (int tn = 0; tn < 8; tn++) {
            int col = bn + wn + tn * 8 + c * 2;
            if (row0 < M) {
                __half2 hv = __floats2half2_rn(acc[tm][tn][0] * s0,
                                               acc[tm][tn][1] * s0);
                *(__half2*)&Ch[(long long)row0 * N + col] = hv;
            }
            if (row1 < M) {
                __half2 hv = __floats2half2_rn(acc[tm][tn][2] * s1,
                                               acc[tm][tn][3] * s1);
                *(__half2*)&Ch[(long long)row1 * N + col] = hv;
            }
        }
    }
}

// ---------------- aggregation: warp per node, wide gathers ----------------
template<int D, bool RELU, bool OUT_HALF>
__global__ __launch_bounds__(256) void agg_warp_kernel(
    const __half* __restrict__ HH, void* __restrict__ Zout,
    const float* __restrict__ bias)
{
    constexpr int VEC = D / 32;          // halves per thread: 8 or 4
    const int wid  = threadIdx.x >> 5;
    const int lane = threadIdx.x & 31;
    const int node = blockIdx.x * 8 + wid;
    if (node >= N_NODES) return;

    const float di = g_dis[node];
    float acc[VEC];

    const __half* selfrow = HH + (long long)node * D + lane * VEC;
    if (VEC == 8) {
        uint4 v = *(const uint4*)selfrow;
        const __half2* h = (const __half2*)&v;
        #pragma unroll
        for (int j = 0; j < 4; j++) {
            float2 p = __half22float2(h[j]);
            acc[2*j] = p.x; acc[2*j+1] = p.y;
        }
    } else {
        uint2 v = *(const uint2*)selfrow;
        const __half2* h = (const __half2*)&v;
        #pragma unroll
        for (int j = 0; j < 2; j++) {
            float2 p = __half22float2(h[j]);
            acc[2*j] = p.x; acc[2*j+1] = p.y;
        }
    }

    int e   = g_offsets[node];
    int end = g_offsets[node + 1];

    for (; e + 4 <= end; e += 4) {
        int n0 = g_src_sorted[e + 0];
        int n1 = g_src_sorted[e + 1];
        int n2 = g_src_sorted[e + 2];
        int n3 = g_src_sorted[e + 3];
        if (VEC == 8) {
            uint4 v0 = *(const uint4*)(HH + (long long)n0 * D + lane * VEC);
            uint4 v1 = *(const uint4*)(HH + (long long)n1 * D + lane * VEC);
            uint4 v2 = *(const uint4*)(HH + (long long)n2 * D + lane * VEC);
            uint4 v3 = *(const uint4*)(HH + (long long)n3 * D + lane * VEC);
            const __half2* h0 = (const __half2*)&v0;
            const __half2* h1 = (const __half2*)&v1;
            const __half2* h2 = (const __half2*)&v2;
            const __half2* h3 = (const __half2*)&v3;
            #pragma unroll
            for (int j = 0; j < 4; j++) {
                float2 p;
                p = __half22float2(h0[j]); acc[2*j] += p.x; acc[2*j+1] += p.y;
                p = __half22float2(h1[j]); acc[2*j] += p.x; acc[2*j+1] += p.y;
                p = __half22float2(h2[j]); acc[2*j] += p.x; acc[2*j+1] += p.y;
                p = __half22float2(h3[j]); acc[2*j] += p.x; acc[2*j+1] += p.y;
            }
        } else {
            uint2 v0 = *(const uint2*)(HH + (long long)n0 * D + lane * VEC);
            uint2 v1 = *(const uint2*)(HH + (long long)n1 * D + lane * VEC);
            uint2 v2 = *(const uint2*)(HH + (long long)n2 * D + lane * VEC);
            uint2 v3 = *(const uint2*)(HH + (long long)n3 * D + lane * VEC);
            const __half2* h0 = (const __half2*)&v0;
            const __half2* h1 = (const __half2*)&v1;
            const __half2* h2 = (const __half2*)&v2;
            const __half2* h3 = (const __half2*)&v3;
            #pragma unroll
            for (int j = 0; j < 2; j++) {
                float2 p;
                p = __half22float2(h0[j]); acc[2*j] += p.x; acc[2*j+1] += p.y;
                p = __half22float2(h1[j]); acc[2*j] += p.x; acc[2*j+1] += p.y;
                p = __half22float2(h2[j]); acc[2*j] += p.x; acc[2*j+1] += p.y;
                p = __half22float2(h3[j]); acc[2*j] += p.x; acc[2*j+1] += p.y;
            }
        }
    }
    for (; e < end; e++) {
        int s = g_src_sorted[e];
        if (VEC == 8) {
            uint4 v = *(const uint4*)(HH + (long long)s * D + lane * VEC);
            const __half2* h = (const __half2*)&v;
            #pragma unroll
            for (int j = 0; j < 4; j++) {
                float2 p = __half22float2(h[j]);
                acc[2*j] += p.x; acc[2*j+1] += p.y;
            }
        } else {
            uint2 v = *(const uint2*)(HH + (long long)s * D + lane * VEC);
            const __half2* h = (const __half2*)&v;
            #pragma unroll
            for (int j = 0; j < 2; j++) {
                float2 p = __half22float2(h[j]);
                acc[2*j] += p.x; acc[2*j+1] += p.y;
            }
        }
    }

    float o[VEC];
    #pragma unroll
    for (int j = 0; j < VEC; j++) {
        o[j] = acc[j] * di + bias[lane * VEC + j];
        if (RELU) o[j] = fmaxf(o[j], 0.f);
    }
    if (OUT_HALF) {
        __half* zp = (__half*)Zout + (long long)node * D + lane * VEC;
        if (VEC == 8) {
            __half2 h[4];
            #pragma unroll
            for (int j = 0; j < 4; j++) h[j] = __floats2half2_rn(o[2*j], o[2*j+1]);
            *(uint4*)zp = *(uint4*)h;
        } else {
            __half2 h[2];
            #pragma unroll
            for (int j = 0; j < 2; j++) h[j] = __floats2half2_rn(o[2*j], o[2*j+1]);
            *(uint2*)zp = *(uint2*)h;
        }
    } else {
        float* zp = (float*)Zout + (long long)node * D + lane * VEC;
        #pragma unroll
        for (int j = 0; j < VEC; j += 4)
            *(float4*)&zp[j] = make_float4(o[j], o[j+1], o[j+2], o[j+3]);
    }
}

// ---------------- decode: y[e] = dot(z2[a], z2[b]) ----------------
__global__ void decode_kernel(const void* __restrict__ eli_raw,
                              const float* __restrict__ Z,
                              float* __restrict__ y, int EL)
{
    int gw   = (blockIdx.x * blockDim.x + threadIdx.x) >> 5;
    int lane = threadIdx.x & 31;
    if (gw >= EL) return;
    int a, b;
    if (g_is64) {
        const long long* p = (const long long*)eli_raw;
        a = (int)p[gw]; b = (int)p[EL + gw];
    } else {
        const int* p = (const int*)eli_raw;
        a = p[gw]; b = p[EL + gw];
    }
    float4 za = *(const float4*)&Z[(long long)a * 128 + lane * 4];
    float4 zb = *(const float4*)&Z[(long long)b * 128 + lane * 4];
    float s = za.x * zb.x + za.y * zb.y + za.z * zb.z + za.w * zb.w;
    #pragma unroll
    for (int o = 16; o; o >>= 1) s += __shfl_down_sync(0xffffffffu, s, o);
    if (lane == 0) y[gw] = s;
}

// ---------------- launch (stream-forked DAG; capturable) ----------------
extern "C" void kernel_launch(void* const* d_in, const int* in_sizes, int n_in,
                              void* d_out, int out_size)
{
    const float* x   = (const float*)d_in[0];
    const void*  ei  = d_in[1];
    const void*  eli = d_in[2];
    const float* W1  = (const float*)d_in[3];
    const float* b1  = (const float*)d_in[4];
    const float* W2  = (const float*)d_in[5];
    const float* b2  = (const float*)d_in[6];
    float*       y   = (float*)d_out;

    const int E  = in_sizes[1] / 2;
    const int EL = in_sizes[2] / 2;

    __half *xhp, *hh1p, *z1hp, *hh2p, *w1tp, *w2tp;
    float  *z2p, *disp;
    cudaGetSymbolAddress((void**)&xhp,  g_xh);
    cudaGetSymbolAddress((void**)&hh1p, g_hh1);
    cudaGetSymbolAddress((void**)&z1hp, g_z1h);
    cudaGetSymbolAddress((void**)&hh2p, g_hh2);
    cudaGetSymbolAddress((void**)&z2p,  g_z2);
    cudaGetSymbolAddress((void**)&disp, g_dis);
    cudaGetSymbolAddress((void**)&w1tp, g_w1t);
    cudaGetSymbolAddress((void**)&w2tp, g_w2t);

    // Host-side stream/event handles, created once OUTSIDE capture (first call
    // is the uncaptured correctness run). Same launch DAG every call ->
    // deterministic. No device memory is allocated by these APIs.
    static cudaStream_t s1 = nullptr, s2 = nullptr;
    static cudaEvent_t ev_start = nullptr, ev_count = nullptr,
                       ev_xconv = nullptr, ev_fill = nullptr;
    if (s1 == nullptr) {
        cudaStreamCreateWithFlags(&s1, cudaStreamNonBlocking);
        cudaStreamCreateWithFlags(&s2, cudaStreamNonBlocking);
        cudaEventCreateWithFlags(&ev_start, cudaEventDisableTiming);
        cudaEventCreateWithFlags(&ev_count, cudaEventDisableTiming);
        cudaEventCreateWithFlags(&ev_xconv, cudaEventDisableTiming);
        cudaEventCreateWithFlags(&ev_fill,  cudaEventDisableTiming);
    }

    const int TB = 256;

    // fork point: s1 branches off the main stream at the start
    cudaEventRecord(ev_start, 0);
    cudaStreamWaitEvent(s1, ev_start, 0);
    // s1: x -> half (independent of graph prep)
    xconv_kernel<<<(N_NODES * D_IN / 4 + TB - 1) / TB, TB, 0, s1>>>(x);
    cudaEventRecord(ev_xconv, s1);

    // main: init (weights + zero counts + detect) -> count
    init_kernel<<<(D_IN * D_H + TB - 1) / TB, TB>>>(W1, W2, (const int*)ei);
    count_kernel<<<(E + TB - 1) / TB, TB>>>(ei, E);
    cudaEventRecord(ev_count, 0);

    // s2: scan + CSR fill (only needed by agg1) overlaps with dis + GEMM1
    cudaStreamWaitEvent(s2, ev_count, 0);
    scan_part1<<<SCAN_B, 1024, 0, s2>>>(N_NODES);
    scan_part2<<<1, 64, 0, s2>>>(SCAN_B, N_NODES);
    scan_part3<<<SCAN_B, 1024, 0, s2>>>(N_NODES);
    fill_kernel<<<(E + TB - 1) / TB, TB, 0, s2>>>(ei, E);
    cudaEventRecord(ev_fill, s2);

    // main: dis -> GEMM1 (needs xconv + dis)
    dis_kernel<<<(N_NODES + TB - 1) / TB, TB>>>();
    cudaStreamWaitEvent(0, ev_xconv, 0);
    {
        dim3 grid(D_H / 128, (N_NODES + 127) / 128);
        hgemm_kernel<<<grid, 256>>>(xhp, w1tp, hh1p, disp, N_NODES, D_H, D_IN);
    }

    // join s2 before agg1 (needs CSR)
    cudaStreamWaitEvent(0, ev_fill, 0);
    agg_warp_kernel<D_H, true, true><<<(N_NODES + 7) / 8, 256>>>(hh1p, z1hp, b1);

    {
        dim3 grid(D_OUT / 128, (N_NODES + 127) / 128);
        hgemm_kernel<<<grid, 256>>>(z1hp, w2tp, hh2p, disp, N_NODES, D_OUT, D_H);
    }
    agg_warp_kernel<D_OUT, false, false><<<(N_NODES + 7) / 8, 256>>>(hh2p, z2p, b2);
    decode_kernel<<<(EL * 32 + TB - 1) / TB, TB>>>(eli, z2p, y, EL);
}